// round 6
// baseline (speedup 1.0000x reference)
#include <cuda_runtime.h>
#include <cuda_fp16.h>
#include <math.h>

#define NN   100000
#define EE   1600000
#define ET   (EE + NN)     // edges + self loops
#define FIN  128
#define DD   64
#define HH   8
#define GG   64
#define NCLS 10
#define SLOPE 0.2f

#define NB_SCAN 98         // ceil(NN/1024)

// ---------------- scratch (device globals) ----------------
__device__ __half2 g_projh[NN * 32];     // h = I @ W, fp16 (1 cache line/row)
__device__ float g_act [NN * DD];        // normalized layer output (layers 1,2)
__device__ float g_als [NN * HH];
__device__ float g_ald [NN * HH];
__device__ int   g_rowptr[NN + 1];
__device__ int   g_col [ET];
__device__ int   g_cnti[NN];
__device__ int   g_rank[ET];
__device__ int   g_bsum[NB_SCAN];
__device__ int   g_boff[NB_SCAN];
__device__ float g_sums[GG * DD];
__device__ float g_cnt [GG];

// ---------------- zero aux ----------------
__global__ void zero_aux_kernel() {
    int i = blockIdx.x * blockDim.x + threadIdx.x;
    if (i < NN) g_cnti[i] = 0;
    if (i < GG * DD) g_sums[i] = 0.f;
    if (i < GG)      g_cnt[i]  = 0.f;
}

// ---------------- CSR build (rank-based, scatter atomic-free) ----------------
__global__ void hist_kernel(const int* __restrict__ ei) {
    int i = blockIdx.x * blockDim.x + threadIdx.x;
    if (i >= ET) return;
    int dst = (i < EE) ? ei[EE + i] : (i - EE);
    g_rank[i] = atomicAdd(&g_cnti[dst], 1);
}

__global__ void scan1_kernel() {
    __shared__ int sd[256];
    const int t = threadIdx.x;
    const int base = blockIdx.x * 1024 + t * 4;
    int v[4];
#pragma unroll
    for (int i = 0; i < 4; i++) {
        int idx = base + i;
        v[i] = (idx < NN) ? g_cnti[idx] : 0;
    }
    int pre[4];
    pre[0] = 0; pre[1] = v[0]; pre[2] = v[0] + v[1]; pre[3] = v[0] + v[1] + v[2];
    int sum = pre[3] + v[3];
    sd[t] = sum;
    __syncthreads();
    for (int off = 1; off < 256; off <<= 1) {
        int x = 0;
        if (t >= off) x = sd[t - off];
        __syncthreads();
        if (t >= off) sd[t] += x;
        __syncthreads();
    }
    int toff = sd[t] - sum;
#pragma unroll
    for (int i = 0; i < 4; i++) {
        int idx = base + i;
        if (idx < NN) g_rowptr[idx] = toff + pre[i];
    }
    if (t == 255) g_bsum[blockIdx.x] = sd[255];
}

__global__ void scan2_kernel() {
    __shared__ int sd[128];
    const int t = threadIdx.x;
    int v = (t < NB_SCAN) ? g_bsum[t] : 0;
    sd[t] = v;
    __syncthreads();
    for (int off = 1; off < 128; off <<= 1) {
        int x = 0;
        if (t >= off) x = sd[t - off];
        __syncthreads();
        if (t >= off) sd[t] += x;
        __syncthreads();
    }
    if (t < NB_SCAN) g_boff[t] = sd[t] - v;
    if (t == NB_SCAN - 1) g_rowptr[NN] = sd[t];
}

__global__ void scan3_kernel() {
    int i = blockIdx.x * blockDim.x + threadIdx.x;
    if (i < NN) g_rowptr[i] += g_boff[i >> 10];
}

__global__ void scatter_kernel(const int* __restrict__ ei) {
    int i = blockIdx.x * blockDim.x + threadIdx.x;
    if (i >= ET) return;
    int src, dst;
    if (i < EE) { src = ei[i]; dst = ei[EE + i]; }
    else        { src = dst = i - EE; }
    g_col[g_rowptr[dst] + g_rank[i]] = src;
}

// ---------------- register-tiled GEMM + attention logits ----------------
template<int K, bool FIRST>
__global__ void gemm_al_kernel(const float* __restrict__ I,
                               const float* __restrict__ W,
                               const float* __restrict__ a_src,
                               const float* __restrict__ a_dst,
                               const float* __restrict__ prev_bias) {
    __shared__ float xs[32][68];
    __shared__ float Wsm[64][64];
    const int t  = threadIdx.x;
    const int tx = t & 15;
    const int ty = t >> 4;
    const int node0 = blockIdx.x * 32;

    float acc[2][4] = {{0.f,0.f,0.f,0.f},{0.f,0.f,0.f,0.f}};
    const int n0 = 2 * ty, n1 = 2 * ty + 1;

    for (int kc = 0; kc < K; kc += 64) {
#pragma unroll
        for (int it = 0; it < 2; it++) {
            int fid  = t + it * 256;
            int node = fid >> 4;
            int kq   = (fid & 15) * 4;
            float4 v;
            if (FIRST) {
                v = *(const float4*)&I[(size_t)(node0 + node) * K + kc + kq];
            } else {
                v = *(const float4*)&g_act[(size_t)(node0 + node) * K + kc + kq];
                v.x += prev_bias[kc + kq    ];
                v.y += prev_bias[kc + kq + 1];
                v.z += prev_bias[kc + kq + 2];
                v.w += prev_bias[kc + kq + 3];
                v.x = v.x > 0.f ? v.x : expm1f(v.x);
                v.y = v.y > 0.f ? v.y : expm1f(v.y);
                v.z = v.z > 0.f ? v.z : expm1f(v.z);
                v.w = v.w > 0.f ? v.w : expm1f(v.w);
            }
            *(float4*)&xs[node][kq] = v;
        }
#pragma unroll
        for (int it = 0; it < 4; it++) {
            int fid = t + it * 256;
            int kk  = fid >> 4;
            int cq  = (fid & 15) * 4;
            *(float4*)&Wsm[kk][cq] = *(const float4*)&W[(size_t)(kc + kk) * DD + cq];
        }
        __syncthreads();
#pragma unroll
        for (int k = 0; k < 64; k++) {
            float xv0 = xs[n0][k];
            float xv1 = xs[n1][k];
            float4 wv = *(const float4*)&Wsm[k][tx * 4];
            acc[0][0] = fmaf(xv0, wv.x, acc[0][0]);
            acc[0][1] = fmaf(xv0, wv.y, acc[0][1]);
            acc[0][2] = fmaf(xv0, wv.z, acc[0][2]);
            acc[0][3] = fmaf(xv0, wv.w, acc[0][3]);
            acc[1][0] = fmaf(xv1, wv.x, acc[1][0]);
            acc[1][1] = fmaf(xv1, wv.y, acc[1][1]);
            acc[1][2] = fmaf(xv1, wv.z, acc[1][2]);
            acc[1][3] = fmaf(xv1, wv.w, acc[1][3]);
        }
        __syncthreads();
    }

    const int gn0 = node0 + n0, gn1 = node0 + n1;
    __half2 h00 = __floats2half2_rn(acc[0][0], acc[0][1]);
    __half2 h01 = __floats2half2_rn(acc[0][2], acc[0][3]);
    __half2 h10 = __floats2half2_rn(acc[1][0], acc[1][1]);
    __half2 h11 = __floats2half2_rn(acc[1][2], acc[1][3]);
    g_projh[(size_t)gn0 * 32 + tx * 2    ] = h00;
    g_projh[(size_t)gn0 * 32 + tx * 2 + 1] = h01;
    g_projh[(size_t)gn1 * 32 + tx * 2    ] = h10;
    g_projh[(size_t)gn1 * 32 + tx * 2 + 1] = h11;

    float s0 = 0.f, d0 = 0.f, s1 = 0.f, d1 = 0.f;
#pragma unroll
    for (int j = 0; j < 4; j++) {
        int c = tx * 4 + j;
        float asv = a_src[c], adv = a_dst[c];
        s0 = fmaf(acc[0][j], asv, s0);
        d0 = fmaf(acc[0][j], adv, d0);
        s1 = fmaf(acc[1][j], asv, s1);
        d1 = fmaf(acc[1][j], adv, d1);
    }
    s0 += __shfl_xor_sync(0xffffffffu, s0, 1);
    d0 += __shfl_xor_sync(0xffffffffu, d0, 1);
    s1 += __shfl_xor_sync(0xffffffffu, s1, 1);
    d1 += __shfl_xor_sync(0xffffffffu, d1, 1);
    if ((tx & 1) == 0) {
        int h = tx >> 1;
        g_als[gn0 * HH + h] = s0;
        g_ald[gn0 * HH + h] = d0;
        g_als[gn1 * HH + h] = s1;
        g_ald[gn1 * HH + h] = d1;
    }
}

// ---------------- CSR edge kernel: warp per dst, paired edges ----------------
// Lanes 0-15 process even edges, 16-31 odd edges; each lane covers 4 cols via
// one uint2 (8B) load; partial acc/dn combined with shfl_xor(16).
#define EW 8
template<bool POOL>
__global__ void __launch_bounds__(256)
edge_csr_kernel(const int* __restrict__ batch, const float* __restrict__ b3) {
    __shared__ int   ss[EW][32];
    __shared__ float ws[EW][32][9];
    const int wl   = threadIdx.x >> 5;
    const int lane = threadIdx.x & 31;
    const int n = blockIdx.x * EW + wl;
    if (n >= NN) return;
    const int rs = g_rowptr[n], re = g_rowptr[n + 1];

    const int half = lane >> 4;     // 0: even edges, 1: odd edges
    const int l    = lane & 15;     // col group: cols 4l..4l+3
    const int h    = l >> 1;        // head of those cols

    const float4 ad0 = *(const float4*)&g_ald[n * HH];
    const float4 ad1 = *(const float4*)&g_ald[n * HH + 4];

    float4 acc = make_float4(0.f, 0.f, 0.f, 0.f);
    float dn = 0.f;

    for (int base = rs; base < re; base += 32) {
        const int e = base + lane;
        if (e < re) {
            int src = g_col[e];
            ss[wl][lane] = src;
            float4 s0 = *(const float4*)&g_als[src * HH];
            float4 s1 = *(const float4*)&g_als[src * HH + 4];
            float ev[8] = { s0.x + ad0.x, s0.y + ad0.y, s0.z + ad0.z, s0.w + ad0.w,
                            s1.x + ad1.x, s1.y + ad1.y, s1.z + ad1.z, s1.w + ad1.w };
#pragma unroll
            for (int hh = 0; hh < 8; hh++) {
                float v = ev[hh] > 0.f ? ev[hh] : SLOPE * ev[hh];
                ws[wl][lane][hh] = __expf(v);
            }
        }
        __syncwarp();
        const int cnt = min(32, re - base);
#pragma unroll 4
        for (int j = half; j < cnt; j += 2) {
            int   sj = ss[wl][j];
            float wj = ws[wl][j][h];
            dn += wj;
            uint2 raw = ((const uint2*)(g_projh + (size_t)sj * 32))[l];
            __half2 p0 = *reinterpret_cast<__half2*>(&raw.x);
            __half2 p1 = *reinterpret_cast<__half2*>(&raw.y);
            float2 f0 = __half22float2(p0);
            float2 f1 = __half22float2(p1);
            acc.x = fmaf(f0.x, wj, acc.x);
            acc.y = fmaf(f0.y, wj, acc.y);
            acc.z = fmaf(f1.x, wj, acc.z);
            acc.w = fmaf(f1.y, wj, acc.w);
        }
        __syncwarp();
    }

    // combine the two edge-halves (lane l and l+16 hold the same cols/head)
    dn    += __shfl_xor_sync(0xffffffffu, dn,    16);
    acc.x += __shfl_xor_sync(0xffffffffu, acc.x, 16);
    acc.y += __shfl_xor_sync(0xffffffffu, acc.y, 16);
    acc.z += __shfl_xor_sync(0xffffffffu, acc.z, 16);
    acc.w += __shfl_xor_sync(0xffffffffu, acc.w, 16);

    if (half == 0) {
        const float inv = 1.f / dn;
        float v0 = acc.x * inv, v1 = acc.y * inv, v2 = acc.z * inv, v3 = acc.w * inv;
        if (POOL) {
            v0 += b3[4 * l];     v1 += b3[4 * l + 1];
            v2 += b3[4 * l + 2]; v3 += b3[4 * l + 3];
            v0 = v0 > 0.f ? v0 : expm1f(v0);
            v1 = v1 > 0.f ? v1 : expm1f(v1);
            v2 = v2 > 0.f ? v2 : expm1f(v2);
            v3 = v3 > 0.f ? v3 : expm1f(v3);
            int g = batch[n];
            atomicAdd(&g_sums[g * DD + 4 * l],     v0);
            atomicAdd(&g_sums[g * DD + 4 * l + 1], v1);
            atomicAdd(&g_sums[g * DD + 4 * l + 2], v2);
            atomicAdd(&g_sums[g * DD + 4 * l + 3], v3);
            if (lane == 0) atomicAdd(&g_cnt[g], 1.0f);
        } else {
            *(float4*)&g_act[(size_t)n * DD + 4 * l] = make_float4(v0, v1, v2, v3);
        }
    }
}

// ---------------- final linear ----------------
__global__ void final_kernel(const float* __restrict__ lin_W,
                             const float* __restrict__ lin_b,
                             float* __restrict__ out) {
    int t = threadIdx.x;
    if (t >= GG * NCLS) return;
    int g = t / NCLS;
    int c = t % NCLS;
    float cnt = fmaxf(g_cnt[g], 1.0f);
    float acc = lin_b[c];
#pragma unroll
    for (int d = 0; d < DD; d++)
        acc = fmaf(g_sums[g * DD + d] / cnt, lin_W[d * NCLS + c], acc);
    out[g * NCLS + c] = acc;
}

// ---------------- launch ----------------
extern "C" void kernel_launch(void* const* d_in, const int* in_sizes, int n_in,
                              void* d_out, int out_size) {
    const float* x      = (const float*)d_in[0];
    const int*   ei     = (const int*)  d_in[1];
    const int*   batch  = (const int*)  d_in[2];
    const float* W1     = (const float*)d_in[3];
    const float* a1s    = (const float*)d_in[4];
    const float* a1d    = (const float*)d_in[5];
    const float* b1     = (const float*)d_in[6];
    const float* W2     = (const float*)d_in[7];
    const float* a2s    = (const float*)d_in[8];
    const float* a2d    = (const float*)d_in[9];
    const float* b2     = (const float*)d_in[10];
    const float* W3     = (const float*)d_in[11];
    const float* a3s    = (const float*)d_in[12];
    const float* a3d    = (const float*)d_in[13];
    const float* b3     = (const float*)d_in[14];
    const float* lin_W  = (const float*)d_in[15];
    const float* lin_b  = (const float*)d_in[16];
    float* out = (float*)d_out;

    const int ngrid = NN / 32;
    const int egrid = (NN + EW - 1) / EW;
    const int etg   = (ET + 255) / 256;

    // ---- CSR build ----
    zero_aux_kernel<<<(NN + 255) / 256, 256>>>();
    hist_kernel<<<etg, 256>>>(ei);
    scan1_kernel<<<NB_SCAN, 256>>>();
    scan2_kernel<<<1, 128>>>();
    scan3_kernel<<<(NN + 255) / 256, 256>>>();
    scatter_kernel<<<etg, 256>>>(ei);

    // ---- layer 1 ----
    gemm_al_kernel<FIN, true><<<ngrid, 256>>>(x, W1, a1s, a1d, nullptr);
    edge_csr_kernel<false><<<egrid, 256>>>(nullptr, nullptr);

    // ---- layer 2 ----
    gemm_al_kernel<DD, false><<<ngrid, 256>>>(nullptr, W2, a2s, a2d, b1);
    edge_csr_kernel<false><<<egrid, 256>>>(nullptr, nullptr);

    // ---- layer 3 (pool fused) ----
    gemm_al_kernel<DD, false><<<ngrid, 256>>>(nullptr, W3, a3s, a3d, b2);
    edge_csr_kernel<true><<<egrid, 256>>>(batch, b3);

    // ---- classify ----
    final_kernel<<<1, GG * NCLS>>>(lin_W, lin_b, out);
}

// round 7
// speedup vs baseline: 1.4830x; 1.4830x over previous
#include <cuda_runtime.h>
#include <cuda_fp16.h>
#include <math.h>

#define NN   100000
#define EE   1600000
#define ET   (EE + NN)     // edges + self loops
#define FIN  128
#define DD   64
#define HH   8
#define GG   64
#define NCLS 10
#define SLOPE 0.2f

#define NB_SCAN 98         // ceil(NN/1024)

// ---------------- scratch (device globals) ----------------
__device__ __half2 g_projh[NN * 32];     // h = I @ W, fp16 (1 cache line/row)
__device__ float g_act [NN * DD];        // normalized layer output (layers 1,2)
__device__ float g_als [NN * HH];
__device__ float g_ald [NN * HH];
__device__ int   g_rowptr[NN + 1];
__device__ int   g_col [ET];
__device__ int   g_cnti[NN];
__device__ int   g_rank[ET];
__device__ int   g_bsum[NB_SCAN];
__device__ int   g_boff[NB_SCAN];
__device__ float g_sums[GG * DD];
__device__ float g_cnt [GG];

// ---------------- zero aux ----------------
__global__ void zero_aux_kernel() {
    int i = blockIdx.x * blockDim.x + threadIdx.x;
    if (i < NN) g_cnti[i] = 0;
    if (i < GG * DD) g_sums[i] = 0.f;
    if (i < GG)      g_cnt[i]  = 0.f;
}

// ---------------- CSR build (rank-based, scatter atomic-free) ----------------
__global__ void hist_kernel(const int* __restrict__ ei) {
    int i = blockIdx.x * blockDim.x + threadIdx.x;
    if (i >= ET) return;
    int dst = (i < EE) ? ei[EE + i] : (i - EE);
    g_rank[i] = atomicAdd(&g_cnti[dst], 1);
}

__global__ void scan1_kernel() {
    __shared__ int sd[256];
    const int t = threadIdx.x;
    const int base = blockIdx.x * 1024 + t * 4;
    int v[4];
#pragma unroll
    for (int i = 0; i < 4; i++) {
        int idx = base + i;
        v[i] = (idx < NN) ? g_cnti[idx] : 0;
    }
    int pre[4];
    pre[0] = 0; pre[1] = v[0]; pre[2] = v[0] + v[1]; pre[3] = v[0] + v[1] + v[2];
    int sum = pre[3] + v[3];
    sd[t] = sum;
    __syncthreads();
    for (int off = 1; off < 256; off <<= 1) {
        int x = 0;
        if (t >= off) x = sd[t - off];
        __syncthreads();
        if (t >= off) sd[t] += x;
        __syncthreads();
    }
    int toff = sd[t] - sum;
#pragma unroll
    for (int i = 0; i < 4; i++) {
        int idx = base + i;
        if (idx < NN) g_rowptr[idx] = toff + pre[i];
    }
    if (t == 255) g_bsum[blockIdx.x] = sd[255];
}

__global__ void scan2_kernel() {
    __shared__ int sd[128];
    const int t = threadIdx.x;
    int v = (t < NB_SCAN) ? g_bsum[t] : 0;
    sd[t] = v;
    __syncthreads();
    for (int off = 1; off < 128; off <<= 1) {
        int x = 0;
        if (t >= off) x = sd[t - off];
        __syncthreads();
        if (t >= off) sd[t] += x;
        __syncthreads();
    }
    if (t < NB_SCAN) g_boff[t] = sd[t] - v;
    if (t == NB_SCAN - 1) g_rowptr[NN] = sd[t];
}

__global__ void scan3_kernel() {
    int i = blockIdx.x * blockDim.x + threadIdx.x;
    if (i < NN) g_rowptr[i] += g_boff[i >> 10];
}

__global__ void scatter_kernel(const int* __restrict__ ei) {
    int i = blockIdx.x * blockDim.x + threadIdx.x;
    if (i >= ET) return;
    int src, dst;
    if (i < EE) { src = ei[i]; dst = ei[EE + i]; }
    else        { src = dst = i - EE; }
    g_col[g_rowptr[dst] + g_rank[i]] = src;
}

// ---------------- register-tiled GEMM + attention logits ----------------
template<int K, bool FIRST>
__global__ void gemm_al_kernel(const float* __restrict__ I,
                               const float* __restrict__ W,
                               const float* __restrict__ a_src,
                               const float* __restrict__ a_dst,
                               const float* __restrict__ prev_bias) {
    __shared__ float xs[32][68];
    __shared__ float Wsm[64][64];
    const int t  = threadIdx.x;
    const int tx = t & 15;
    const int ty = t >> 4;
    const int node0 = blockIdx.x * 32;

    float acc[2][4] = {{0.f,0.f,0.f,0.f},{0.f,0.f,0.f,0.f}};
    const int n0 = 2 * ty, n1 = 2 * ty + 1;

    for (int kc = 0; kc < K; kc += 64) {
#pragma unroll
        for (int it = 0; it < 2; it++) {
            int fid  = t + it * 256;
            int node = fid >> 4;
            int kq   = (fid & 15) * 4;
            float4 v;
            if (FIRST) {
                v = *(const float4*)&I[(size_t)(node0 + node) * K + kc + kq];
            } else {
                v = *(const float4*)&g_act[(size_t)(node0 + node) * K + kc + kq];
                v.x += prev_bias[kc + kq    ];
                v.y += prev_bias[kc + kq + 1];
                v.z += prev_bias[kc + kq + 2];
                v.w += prev_bias[kc + kq + 3];
                v.x = v.x > 0.f ? v.x : expm1f(v.x);
                v.y = v.y > 0.f ? v.y : expm1f(v.y);
                v.z = v.z > 0.f ? v.z : expm1f(v.z);
                v.w = v.w > 0.f ? v.w : expm1f(v.w);
            }
            *(float4*)&xs[node][kq] = v;
        }
#pragma unroll
        for (int it = 0; it < 4; it++) {
            int fid = t + it * 256;
            int kk  = fid >> 4;
            int cq  = (fid & 15) * 4;
            *(float4*)&Wsm[kk][cq] = *(const float4*)&W[(size_t)(kc + kk) * DD + cq];
        }
        __syncthreads();
#pragma unroll
        for (int k = 0; k < 64; k++) {
            float xv0 = xs[n0][k];
            float xv1 = xs[n1][k];
            float4 wv = *(const float4*)&Wsm[k][tx * 4];
            acc[0][0] = fmaf(xv0, wv.x, acc[0][0]);
            acc[0][1] = fmaf(xv0, wv.y, acc[0][1]);
            acc[0][2] = fmaf(xv0, wv.z, acc[0][2]);
            acc[0][3] = fmaf(xv0, wv.w, acc[0][3]);
            acc[1][0] = fmaf(xv1, wv.x, acc[1][0]);
            acc[1][1] = fmaf(xv1, wv.y, acc[1][1]);
            acc[1][2] = fmaf(xv1, wv.z, acc[1][2]);
            acc[1][3] = fmaf(xv1, wv.w, acc[1][3]);
        }
        __syncthreads();
    }

    const int gn0 = node0 + n0, gn1 = node0 + n1;
    __half2 h00 = __floats2half2_rn(acc[0][0], acc[0][1]);
    __half2 h01 = __floats2half2_rn(acc[0][2], acc[0][3]);
    __half2 h10 = __floats2half2_rn(acc[1][0], acc[1][1]);
    __half2 h11 = __floats2half2_rn(acc[1][2], acc[1][3]);
    g_projh[(size_t)gn0 * 32 + tx * 2    ] = h00;
    g_projh[(size_t)gn0 * 32 + tx * 2 + 1] = h01;
    g_projh[(size_t)gn1 * 32 + tx * 2    ] = h10;
    g_projh[(size_t)gn1 * 32 + tx * 2 + 1] = h11;

    float s0 = 0.f, d0 = 0.f, s1 = 0.f, d1 = 0.f;
#pragma unroll
    for (int j = 0; j < 4; j++) {
        int c = tx * 4 + j;
        float asv = a_src[c], adv = a_dst[c];
        s0 = fmaf(acc[0][j], asv, s0);
        d0 = fmaf(acc[0][j], adv, d0);
        s1 = fmaf(acc[1][j], asv, s1);
        d1 = fmaf(acc[1][j], adv, d1);
    }
    s0 += __shfl_xor_sync(0xffffffffu, s0, 1);
    d0 += __shfl_xor_sync(0xffffffffu, d0, 1);
    s1 += __shfl_xor_sync(0xffffffffu, s1, 1);
    d1 += __shfl_xor_sync(0xffffffffu, d1, 1);
    if ((tx & 1) == 0) {
        int h = tx >> 1;
        g_als[gn0 * HH + h] = s0;
        g_ald[gn0 * HH + h] = d0;
        g_als[gn1 * HH + h] = s1;
        g_ald[gn1 * HH + h] = d1;
    }
}

// ---------------- CSR edge kernel: warp per dst (round-4 loop shape) ----------
// One edge per j; all 32 lanes read one fp16 proj row (128B = 1 L2 line).
// POOL=true (layer 3): apply elu(.+b3) and pool directly, skip act write.
#define EW 8
template<bool POOL>
__global__ void __launch_bounds__(256)
edge_csr_kernel(const int* __restrict__ batch, const float* __restrict__ b3) {
    __shared__ int   ss[EW][32];
    __shared__ float ws[EW][32][9];
    const int wl   = threadIdx.x >> 5;
    const int lane = threadIdx.x & 31;
    const int n = blockIdx.x * EW + wl;
    if (n >= NN) return;
    const int rs = g_rowptr[n], re = g_rowptr[n + 1];

    const float4 ad0 = *(const float4*)&g_ald[n * HH];
    const float4 ad1 = *(const float4*)&g_ald[n * HH + 4];

    float2 acc = make_float2(0.f, 0.f);
    float dn = 0.f;
    const int h = lane >> 2;          // head of cols 2*lane, 2*lane+1

    for (int base = rs; base < re; base += 32) {
        const int e = base + lane;
        if (e < re) {
            int src = g_col[e];
            ss[wl][lane] = src;
            float4 s0 = *(const float4*)&g_als[src * HH];
            float4 s1 = *(const float4*)&g_als[src * HH + 4];
            float ev[8] = { s0.x + ad0.x, s0.y + ad0.y, s0.z + ad0.z, s0.w + ad0.w,
                            s1.x + ad1.x, s1.y + ad1.y, s1.z + ad1.z, s1.w + ad1.w };
#pragma unroll
            for (int hh = 0; hh < 8; hh++) {
                float v = ev[hh] > 0.f ? ev[hh] : SLOPE * ev[hh];
                ws[wl][lane][hh] = __expf(v);
            }
        }
        __syncwarp();
        const int cnt = min(32, re - base);
#pragma unroll 4
        for (int j = 0; j < cnt; j++) {
            int   sj = ss[wl][j];
            float wj = ws[wl][j][h];
            dn += wj;
            float2 p = __half22float2(g_projh[(size_t)sj * 32 + lane]);
            acc.x = fmaf(p.x, wj, acc.x);
            acc.y = fmaf(p.y, wj, acc.y);
        }
        __syncwarp();
    }
    const float inv = 1.f / dn;
    if (POOL) {
        float v0 = acc.x * inv + b3[2 * lane];
        float v1 = acc.y * inv + b3[2 * lane + 1];
        v0 = v0 > 0.f ? v0 : expm1f(v0);
        v1 = v1 > 0.f ? v1 : expm1f(v1);
        int g = batch[n];
        atomicAdd(&g_sums[g * DD + 2 * lane],     v0);
        atomicAdd(&g_sums[g * DD + 2 * lane + 1], v1);
        if (lane == 0) atomicAdd(&g_cnt[g], 1.0f);
    } else {
        *(float2*)&g_act[(size_t)n * DD + 2 * lane] =
            make_float2(acc.x * inv, acc.y * inv);
    }
}

// ---------------- final linear ----------------
__global__ void final_kernel(const float* __restrict__ lin_W,
                             const float* __restrict__ lin_b,
                             float* __restrict__ out) {
    int t = threadIdx.x;
    if (t >= GG * NCLS) return;
    int g = t / NCLS;
    int c = t % NCLS;
    float cnt = fmaxf(g_cnt[g], 1.0f);
    float acc = lin_b[c];
#pragma unroll
    for (int d = 0; d < DD; d++)
        acc = fmaf(g_sums[g * DD + d] / cnt, lin_W[d * NCLS + c], acc);
    out[g * NCLS + c] = acc;
}

// ---------------- launch ----------------
extern "C" void kernel_launch(void* const* d_in, const int* in_sizes, int n_in,
                              void* d_out, int out_size) {
    const float* x      = (const float*)d_in[0];
    const int*   ei     = (const int*)  d_in[1];
    const int*   batch  = (const int*)  d_in[2];
    const float* W1     = (const float*)d_in[3];
    const float* a1s    = (const float*)d_in[4];
    const float* a1d    = (const float*)d_in[5];
    const float* b1     = (const float*)d_in[6];
    const float* W2     = (const float*)d_in[7];
    const float* a2s    = (const float*)d_in[8];
    const float* a2d    = (const float*)d_in[9];
    const float* b2     = (const float*)d_in[10];
    const float* W3     = (const float*)d_in[11];
    const float* a3s    = (const float*)d_in[12];
    const float* a3d    = (const float*)d_in[13];
    const float* b3     = (const float*)d_in[14];
    const float* lin_W  = (const float*)d_in[15];
    const float* lin_b  = (const float*)d_in[16];
    float* out = (float*)d_out;

    const int ngrid = NN / 32;
    const int egrid = (NN + EW - 1) / EW;
    const int etg   = (ET + 255) / 256;

    // ---- CSR build ----
    zero_aux_kernel<<<(NN + 255) / 256, 256>>>();
    hist_kernel<<<etg, 256>>>(ei);
    scan1_kernel<<<NB_SCAN, 256>>>();
    scan2_kernel<<<1, 128>>>();
    scan3_kernel<<<(NN + 255) / 256, 256>>>();
    scatter_kernel<<<etg, 256>>>(ei);

    // ---- layer 1 ----
    gemm_al_kernel<FIN, true><<<ngrid, 256>>>(x, W1, a1s, a1d, nullptr);
    edge_csr_kernel<false><<<egrid, 256>>>(nullptr, nullptr);

    // ---- layer 2 ----
    gemm_al_kernel<DD, false><<<ngrid, 256>>>(nullptr, W2, a2s, a2d, b1);
    edge_csr_kernel<false><<<egrid, 256>>>(nullptr, nullptr);

    // ---- layer 3 (pool fused) ----
    gemm_al_kernel<DD, false><<<ngrid, 256>>>(nullptr, W3, a3s, a3d, b2);
    edge_csr_kernel<true><<<egrid, 256>>>(batch, b3);

    // ---- classify ----
    final_kernel<<<1, GG * NCLS>>>(lin_W, lin_b, out);
}

// round 8
// speedup vs baseline: 1.8144x; 1.2235x over previous
#include <cuda_runtime.h>
#include <math.h>

#define NN   100000
#define EE   1600000
#define ET   (EE + NN)     // edges + self loops
#define FIN  128
#define DD   64
#define HH   8
#define GG   64
#define NCLS 10
#define SLOPE 0.2f

// ---------------- scratch (device globals) ----------------
__device__ float g_proj[NN * DD];        // h = I @ W (fp32)
__device__ float g_act [NN * DD];        // normalized layer output
__device__ float g_als [NN * HH];
__device__ float g_ald [NN * HH];
__device__ int   g_rowptr[NN + 1];
__device__ int   g_col [ET];
__device__ int   g_cnti[NN];             // zero-initialized; re-zeroed by scatter tail
__device__ int   g_rank[ET];
__device__ float g_sums[GG * DD];        // zero-initialized; re-zeroed by final tail
__device__ float g_cnt [GG];

// ---------------- CSR build ----------------
// hist records each edge's within-dst rank -> scatter is atomic-free.
__global__ void hist_kernel(const int* __restrict__ ei) {
    int i = blockIdx.x * blockDim.x + threadIdx.x;
    if (i >= ET) return;
    int dst = (i < EE) ? ei[EE + i] : (i - EE);
    g_rank[i] = atomicAdd(&g_cnti[dst], 1);
}

// Single-block fused exclusive scan of g_cnti -> g_rowptr (1024 threads, 98 chunks).
__global__ void scanF_kernel() {
    __shared__ int wsum[32];
    __shared__ int woff[32];
    __shared__ int tot;
    const int t = threadIdx.x;
    const int lane = t & 31, wid = t >> 5;
    int run = 0;
    for (int chunk = 0; chunk < 98; chunk++) {
        int idx = chunk * 1024 + t;
        int v = (idx < NN) ? g_cnti[idx] : 0;
        int inc = v;
#pragma unroll
        for (int off = 1; off < 32; off <<= 1) {
            int x = __shfl_up_sync(0xffffffffu, inc, off);
            if (lane >= off) inc += x;
        }
        if (lane == 31) wsum[wid] = inc;
        __syncthreads();
        if (wid == 0) {
            int s = wsum[lane];
            int is = s;
#pragma unroll
            for (int off = 1; off < 32; off <<= 1) {
                int x = __shfl_up_sync(0xffffffffu, is, off);
                if (lane >= off) is += x;
            }
            woff[lane] = is - s;           // exclusive warp offset
            if (lane == 31) tot = is;      // chunk total
        }
        __syncthreads();
        if (idx < NN) g_rowptr[idx] = run + woff[wid] + (inc - v);
        run += tot;
        // no third sync needed: next chunk's wsum/tot writes are gated by the
        // next chunk's first __syncthreads.
    }
    if (t == 0) g_rowptr[NN] = run;
}

__global__ void scatter_kernel(const int* __restrict__ ei) {
    int i = blockIdx.x * blockDim.x + threadIdx.x;
    if (i < NN) g_cnti[i] = 0;            // re-zero for next replay's hist
    if (i >= ET) return;
    int src, dst;
    if (i < EE) { src = ei[i]; dst = ei[EE + i]; }
    else        { src = dst = i - EE; }
    g_col[g_rowptr[dst] + g_rank[i]] = src;
}

// ---------------- register-tiled GEMM + attention logits (R4 config) --------
template<int K, bool FIRST>
__global__ void gemm_al_kernel(const float* __restrict__ I,
                               const float* __restrict__ W,
                               const float* __restrict__ a_src,
                               const float* __restrict__ a_dst,
                               const float* __restrict__ prev_bias) {
    __shared__ float xs[32][68];
    __shared__ float Wsm[64][64];
    const int t  = threadIdx.x;
    const int tx = t & 15;
    const int ty = t >> 4;
    const int node0 = blockIdx.x * 32;

    float acc[2][4] = {{0.f,0.f,0.f,0.f},{0.f,0.f,0.f,0.f}};
    const int n0 = 2 * ty, n1 = 2 * ty + 1;

    for (int kc = 0; kc < K; kc += 64) {
#pragma unroll
        for (int it = 0; it < 2; it++) {
            int fid  = t + it * 256;
            int node = fid >> 4;
            int kq   = (fid & 15) * 4;
            float4 v;
            if (FIRST) {
                v = *(const float4*)&I[(size_t)(node0 + node) * K + kc + kq];
            } else {
                v = *(const float4*)&g_act[(size_t)(node0 + node) * K + kc + kq];
                v.x += prev_bias[kc + kq    ];
                v.y += prev_bias[kc + kq + 1];
                v.z += prev_bias[kc + kq + 2];
                v.w += prev_bias[kc + kq + 3];
                v.x = v.x > 0.f ? v.x : expm1f(v.x);
                v.y = v.y > 0.f ? v.y : expm1f(v.y);
                v.z = v.z > 0.f ? v.z : expm1f(v.z);
                v.w = v.w > 0.f ? v.w : expm1f(v.w);
            }
            *(float4*)&xs[node][kq] = v;
        }
#pragma unroll
        for (int it = 0; it < 4; it++) {
            int fid = t + it * 256;
            int kk  = fid >> 4;
            int cq  = (fid & 15) * 4;
            *(float4*)&Wsm[kk][cq] = *(const float4*)&W[(size_t)(kc + kk) * DD + cq];
        }
        __syncthreads();
#pragma unroll
        for (int k = 0; k < 64; k++) {
            float xv0 = xs[n0][k];
            float xv1 = xs[n1][k];
            float4 wv = *(const float4*)&Wsm[k][tx * 4];
            acc[0][0] = fmaf(xv0, wv.x, acc[0][0]);
            acc[0][1] = fmaf(xv0, wv.y, acc[0][1]);
            acc[0][2] = fmaf(xv0, wv.z, acc[0][2]);
            acc[0][3] = fmaf(xv0, wv.w, acc[0][3]);
            acc[1][0] = fmaf(xv1, wv.x, acc[1][0]);
            acc[1][1] = fmaf(xv1, wv.y, acc[1][1]);
            acc[1][2] = fmaf(xv1, wv.z, acc[1][2]);
            acc[1][3] = fmaf(xv1, wv.w, acc[1][3]);
        }
        __syncthreads();
    }

    const int gn0 = node0 + n0, gn1 = node0 + n1;
    *(float4*)&g_proj[(size_t)gn0 * DD + tx * 4] =
        make_float4(acc[0][0], acc[0][1], acc[0][2], acc[0][3]);
    *(float4*)&g_proj[(size_t)gn1 * DD + tx * 4] =
        make_float4(acc[1][0], acc[1][1], acc[1][2], acc[1][3]);

    float s0 = 0.f, d0 = 0.f, s1 = 0.f, d1 = 0.f;
#pragma unroll
    for (int j = 0; j < 4; j++) {
        int c = tx * 4 + j;
        float asv = a_src[c], adv = a_dst[c];
        s0 = fmaf(acc[0][j], asv, s0);
        d0 = fmaf(acc[0][j], adv, d0);
        s1 = fmaf(acc[1][j], asv, s1);
        d1 = fmaf(acc[1][j], adv, d1);
    }
    s0 += __shfl_xor_sync(0xffffffffu, s0, 1);
    d0 += __shfl_xor_sync(0xffffffffu, d0, 1);
    s1 += __shfl_xor_sync(0xffffffffu, s1, 1);
    d1 += __shfl_xor_sync(0xffffffffu, d1, 1);
    if ((tx & 1) == 0) {
        int h = tx >> 1;
        g_als[gn0 * HH + h] = s0;
        g_ald[gn0 * HH + h] = d0;
        g_als[gn1 * HH + h] = s1;
        g_ald[gn1 * HH + h] = d1;
    }
}

// ---------------- CSR edge kernel (exact R4 shape, fp32 proj) ---------------
#define EW 8
__global__ void edge_csr_kernel() {
    __shared__ int   ss[EW][32];
    __shared__ float ws[EW][32][9];
    const int wl   = threadIdx.x >> 5;
    const int lane = threadIdx.x & 31;
    const int n = blockIdx.x * EW + wl;
    if (n >= NN) return;
    const int rs = g_rowptr[n], re = g_rowptr[n + 1];

    const float4 ad0 = *(const float4*)&g_ald[n * HH];
    const float4 ad1 = *(const float4*)&g_ald[n * HH + 4];

    float2 acc = make_float2(0.f, 0.f);
    float dn = 0.f;
    const int h = lane >> 2;

    for (int base = rs; base < re; base += 32) {
        const int e = base + lane;
        if (e < re) {
            int src = g_col[e];
            ss[wl][lane] = src;
            float4 s0 = *(const float4*)&g_als[src * HH];
            float4 s1 = *(const float4*)&g_als[src * HH + 4];
            float ev[8] = { s0.x + ad0.x, s0.y + ad0.y, s0.z + ad0.z, s0.w + ad0.w,
                            s1.x + ad1.x, s1.y + ad1.y, s1.z + ad1.z, s1.w + ad1.w };
#pragma unroll
            for (int hh = 0; hh < 8; hh++) {
                float v = ev[hh] > 0.f ? ev[hh] : SLOPE * ev[hh];
                ws[wl][lane][hh] = __expf(v);
            }
        }
        __syncwarp();
        const int cnt = min(32, re - base);
#pragma unroll 4
        for (int j = 0; j < cnt; j++) {
            int   sj = ss[wl][j];
            float wj = ws[wl][j][h];
            dn += wj;
            float2 p = *(const float2*)&g_proj[(size_t)sj * DD + 2 * lane];
            acc.x = fmaf(p.x, wj, acc.x);
            acc.y = fmaf(p.y, wj, acc.y);
        }
        __syncwarp();
    }
    const float inv = 1.f / dn;
    *(float2*)&g_act[(size_t)n * DD + 2 * lane] = make_float2(acc.x * inv, acc.y * inv);
}

// ---------------- hierarchical pool (flush-on-graph-change) ----------------
// batch is sorted: each thread scans an increasing node subsequence of its
// block's 256-node range and only atomics on graph boundaries (~30k total).
__global__ void pool2_kernel(const int* __restrict__ batch,
                             const float* __restrict__ b3) {
    const int t = threadIdx.x;          // 256
    const int d = t & 63;
    const int r = t >> 6;               // 0..3
    const int start = blockIdx.x * 256;
    const float bias = b3[d];
    int curg = -1;
    float accv = 0.f, accc = 0.f;
    for (int k = 0; k < 64; k++) {
        int n = start + r + k * 4;
        if (n >= NN) break;
        int g = batch[n];
        if (g != curg) {
            if (curg >= 0) {
                atomicAdd(&g_sums[curg * DD + d], accv);
                if (d == 0) atomicAdd(&g_cnt[curg], accc);
            }
            curg = g; accv = 0.f; accc = 0.f;
        }
        float v = g_act[(size_t)n * DD + d] + bias;
        v = v > 0.f ? v : expm1f(v);
        accv += v;
        accc += 1.f;
    }
    if (curg >= 0) {
        atomicAdd(&g_sums[curg * DD + d], accv);
        if (d == 0) atomicAdd(&g_cnt[curg], accc);
    }
}

// ---------------- final linear (+ re-zero pool buffers for next replay) -----
__global__ void final_kernel(const float* __restrict__ lin_W,
                             const float* __restrict__ lin_b,
                             float* __restrict__ out) {
    int t = threadIdx.x;                // 640
    int g = t / NCLS;
    int c = t % NCLS;
    float cnt = fmaxf(g_cnt[g], 1.0f);
    float acc = lin_b[c];
#pragma unroll
    for (int d = 0; d < DD; d++)
        acc = fmaf(g_sums[g * DD + d] / cnt, lin_W[d * NCLS + c], acc);
    out[g * NCLS + c] = acc;
    __syncthreads();                    // all reads of g_sums/g_cnt done
    for (int i = t; i < GG * DD; i += 640) g_sums[i] = 0.f;
    if (t < GG) g_cnt[t] = 0.f;
}

// ---------------- launch ----------------
extern "C" void kernel_launch(void* const* d_in, const int* in_sizes, int n_in,
                              void* d_out, int out_size) {
    const float* x      = (const float*)d_in[0];
    const int*   ei     = (const int*)  d_in[1];
    const int*   batch  = (const int*)  d_in[2];
    const float* W1     = (const float*)d_in[3];
    const float* a1s    = (const float*)d_in[4];
    const float* a1d    = (const float*)d_in[5];
    const float* b1     = (const float*)d_in[6];
    const float* W2     = (const float*)d_in[7];
    const float* a2s    = (const float*)d_in[8];
    const float* a2d    = (const float*)d_in[9];
    const float* b2     = (const float*)d_in[10];
    const float* W3     = (const float*)d_in[11];
    const float* a3s    = (const float*)d_in[12];
    const float* a3d    = (const float*)d_in[13];
    const float* b3     = (const float*)d_in[14];
    const float* lin_W  = (const float*)d_in[15];
    const float* lin_b  = (const float*)d_in[16];
    float* out = (float*)d_out;

    const int ngrid = NN / 32;
    const int egrid = (NN + EW - 1) / EW;
    const int etg   = (ET + 255) / 256;
    const int pgrid = (NN + 255) / 256;

    // gemm1 first (no CSR dependency) -> profiled launch index 3 = scatter
    gemm_al_kernel<FIN, true><<<ngrid, 256>>>(x, W1, a1s, a1d, nullptr);   // 0
    hist_kernel<<<etg, 256>>>(ei);                                         // 1
    scanF_kernel<<<1, 1024>>>();                                           // 2
    scatter_kernel<<<etg, 256>>>(ei);                                      // 3
    edge_csr_kernel<<<egrid, 256>>>();                                     // 4

    gemm_al_kernel<DD, false><<<ngrid, 256>>>(nullptr, W2, a2s, a2d, b1);  // 5
    edge_csr_kernel<<<egrid, 256>>>();                                     // 6

    gemm_al_kernel<DD, false><<<ngrid, 256>>>(nullptr, W3, a3s, a3d, b2);  // 7
    edge_csr_kernel<<<egrid, 256>>>();                                     // 8

    pool2_kernel<<<pgrid, 256>>>(batch, b3);                               // 9
    final_kernel<<<1, GG * NCLS>>>(lin_W, lin_b, out);                     // 10
}

// round 9
// speedup vs baseline: 1.8927x; 1.0432x over previous
#include <cuda_runtime.h>
#include <math.h>

#define NN   100000
#define EE   1600000
#define ET   (EE + NN)     // edges + self loops
#define FIN  128
#define DD   64
#define HH   8
#define GG   64
#define NCLS 10
#define SLOPE 0.2f

// ---------------- scratch (device globals) ----------------
__device__ float g_proj[NN * DD];        // h = I @ W (fp32)
__device__ float g_act [NN * DD];        // normalized layer output
__device__ float g_als [NN * HH];
__device__ float g_ald [NN * HH];
__device__ int   g_rowptr[NN + 1];
__device__ int   g_col [ET];
__device__ int   g_cnti[NN];             // zero-init; re-zeroed by scatter tail
__device__ int   g_rank[ET];
__device__ float g_sums[GG * DD];        // zero-init; re-zeroed by final tail
__device__ float g_cnt [GG];

// ---------------- CSR build ----------------
__global__ void hist_kernel(const int* __restrict__ ei) {
    int i = blockIdx.x * blockDim.x + threadIdx.x;
    if (i >= ET) return;
    int dst = (i < EE) ? ei[EE + i] : (i - EE);
    g_rank[i] = atomicAdd(&g_cnti[dst], 1);
}

// Single-block fused exclusive scan of g_cnti -> g_rowptr.
__global__ void scanF_kernel() {
    __shared__ int wsum[32];
    __shared__ int woff[32];
    __shared__ int tot;
    const int t = threadIdx.x;
    const int lane = t & 31, wid = t >> 5;
    int run = 0;
    for (int chunk = 0; chunk < 98; chunk++) {
        int idx = chunk * 1024 + t;
        int v = (idx < NN) ? g_cnti[idx] : 0;
        int inc = v;
#pragma unroll
        for (int off = 1; off < 32; off <<= 1) {
            int x = __shfl_up_sync(0xffffffffu, inc, off);
            if (lane >= off) inc += x;
        }
        if (lane == 31) wsum[wid] = inc;
        __syncthreads();
        if (wid == 0) {
            int s = wsum[lane];
            int is = s;
#pragma unroll
            for (int off = 1; off < 32; off <<= 1) {
                int x = __shfl_up_sync(0xffffffffu, is, off);
                if (lane >= off) is += x;
            }
            woff[lane] = is - s;
            if (lane == 31) tot = is;
        }
        __syncthreads();
        if (idx < NN) g_rowptr[idx] = run + woff[wid] + (inc - v);
        run += tot;
    }
    if (t == 0) g_rowptr[NN] = run;
}

__global__ void scatter_kernel(const int* __restrict__ ei) {
    int i = blockIdx.x * blockDim.x + threadIdx.x;
    if (i < NN) g_cnti[i] = 0;
    if (i >= ET) return;
    int src, dst;
    if (i < EE) { src = ei[i]; dst = ei[EE + i]; }
    else        { src = dst = i - EE; }
    g_col[g_rowptr[dst] + g_rank[i]] = src;
}

// ---------------- register-tiled GEMM + attention logits --------------------
template<int K, bool FIRST>
__global__ void gemm_al_kernel(const float* __restrict__ I,
                               const float* __restrict__ W,
                               const float* __restrict__ a_src,
                               const float* __restrict__ a_dst,
                               const float* __restrict__ prev_bias) {
    __shared__ float xs[32][68];
    __shared__ float Wsm[64][64];
    const int t  = threadIdx.x;
    const int tx = t & 15;
    const int ty = t >> 4;
    const int node0 = blockIdx.x * 32;

    float acc[2][4] = {{0.f,0.f,0.f,0.f},{0.f,0.f,0.f,0.f}};
    const int n0 = 2 * ty, n1 = 2 * ty + 1;

    for (int kc = 0; kc < K; kc += 64) {
#pragma unroll
        for (int it = 0; it < 2; it++) {
            int fid  = t + it * 256;
            int node = fid >> 4;
            int kq   = (fid & 15) * 4;
            float4 v;
            if (FIRST) {
                v = *(const float4*)&I[(size_t)(node0 + node) * K + kc + kq];
            } else {
                v = *(const float4*)&g_act[(size_t)(node0 + node) * K + kc + kq];
                v.x += prev_bias[kc + kq    ];
                v.y += prev_bias[kc + kq + 1];
                v.z += prev_bias[kc + kq + 2];
                v.w += prev_bias[kc + kq + 3];
                v.x = v.x > 0.f ? v.x : expm1f(v.x);
                v.y = v.y > 0.f ? v.y : expm1f(v.y);
                v.z = v.z > 0.f ? v.z : expm1f(v.z);
                v.w = v.w > 0.f ? v.w : expm1f(v.w);
            }
            *(float4*)&xs[node][kq] = v;
        }
#pragma unroll
        for (int it = 0; it < 4; it++) {
            int fid = t + it * 256;
            int kk  = fid >> 4;
            int cq  = (fid & 15) * 4;
            *(float4*)&Wsm[kk][cq] = *(const float4*)&W[(size_t)(kc + kk) * DD + cq];
        }
        __syncthreads();
#pragma unroll
        for (int k = 0; k < 64; k++) {
            float xv0 = xs[n0][k];
            float xv1 = xs[n1][k];
            float4 wv = *(const float4*)&Wsm[k][tx * 4];
            acc[0][0] = fmaf(xv0, wv.x, acc[0][0]);
            acc[0][1] = fmaf(xv0, wv.y, acc[0][1]);
            acc[0][2] = fmaf(xv0, wv.z, acc[0][2]);
            acc[0][3] = fmaf(xv0, wv.w, acc[0][3]);
            acc[1][0] = fmaf(xv1, wv.x, acc[1][0]);
            acc[1][1] = fmaf(xv1, wv.y, acc[1][1]);
            acc[1][2] = fmaf(xv1, wv.z, acc[1][2]);
            acc[1][3] = fmaf(xv1, wv.w, acc[1][3]);
        }
        __syncthreads();
    }

    const int gn0 = node0 + n0, gn1 = node0 + n1;
    *(float4*)&g_proj[(size_t)gn0 * DD + tx * 4] =
        make_float4(acc[0][0], acc[0][1], acc[0][2], acc[0][3]);
    *(float4*)&g_proj[(size_t)gn1 * DD + tx * 4] =
        make_float4(acc[1][0], acc[1][1], acc[1][2], acc[1][3]);

    float s0 = 0.f, d0 = 0.f, s1 = 0.f, d1 = 0.f;
#pragma unroll
    for (int j = 0; j < 4; j++) {
        int c = tx * 4 + j;
        float asv = a_src[c], adv = a_dst[c];
        s0 = fmaf(acc[0][j], asv, s0);
        d0 = fmaf(acc[0][j], adv, d0);
        s1 = fmaf(acc[1][j], asv, s1);
        d1 = fmaf(acc[1][j], adv, d1);
    }
    s0 += __shfl_xor_sync(0xffffffffu, s0, 1);
    d0 += __shfl_xor_sync(0xffffffffu, d0, 1);
    s1 += __shfl_xor_sync(0xffffffffu, s1, 1);
    d1 += __shfl_xor_sync(0xffffffffu, d1, 1);
    if ((tx & 1) == 0) {
        int h = tx >> 1;
        g_als[gn0 * HH + h] = s0;
        g_ald[gn0 * HH + h] = d0;
        g_als[gn1 * HH + h] = s1;
        g_ald[gn1 * HH + h] = d1;
    }
}

// ---------------- dual-dst CSR edge kernel ----------------------------------
// Warp = 2 dst nodes (half-warps). Lane (half, l): cols 4l..4l+3 of its dst.
// One LDG.128 per j serves both halves (2 proj rows, 512B in flight).
// Out-of-range edges are masked by w=0 at staging -> unconditional inner loop.
#define EW 8
__global__ void __launch_bounds__(256) edge_csr_kernel() {
    __shared__ int   ss[EW][2][16];
    __shared__ float ws[EW][2][16][9];
    const int wl   = threadIdx.x >> 5;
    const int lane = threadIdx.x & 31;
    const int half = lane >> 4;
    const int l    = lane & 15;
    const int hh   = l >> 1;                 // head of cols 4l..4l+3
    const int n = blockIdx.x * (2 * EW) + 2 * wl + half;   // NN%16==0: always valid

    const int rs = g_rowptr[n], re = g_rowptr[n + 1];
    const int len  = re - rs;
    const int olen = __shfl_xor_sync(0xffffffffu, len, 16);
    const int mlen = max(len, olen);

    const float4 ad0 = *(const float4*)&g_ald[n * HH];
    const float4 ad1 = *(const float4*)&g_ald[n * HH + 4];

    float4 acc = make_float4(0.f, 0.f, 0.f, 0.f);
    float dn = 0.f;

    for (int base = 0; base < mlen; base += 16) {
        const int e = rs + base + l;
        const bool valid = (e < re);
        int src = valid ? g_col[e] : 0;
        ss[wl][half][l] = src;
        {
            float4 s0 = *(const float4*)&g_als[src * HH];
            float4 s1 = *(const float4*)&g_als[src * HH + 4];
            float ev[8] = { s0.x + ad0.x, s0.y + ad0.y, s0.z + ad0.z, s0.w + ad0.w,
                            s1.x + ad1.x, s1.y + ad1.y, s1.z + ad1.z, s1.w + ad1.w };
            const float m = valid ? 1.f : 0.f;
#pragma unroll
            for (int k = 0; k < 8; k++) {
                float v = ev[k] > 0.f ? ev[k] : SLOPE * ev[k];
                ws[wl][half][l][k] = m * __expf(v);
            }
        }
        __syncwarp();
        const int cnt = min(16, mlen - base);
#pragma unroll 4
        for (int j = 0; j < cnt; j++) {
            int   sj = ss[wl][half][j];
            float wj = ws[wl][half][j][hh];
            dn += wj;
            float4 p = *(const float4*)&g_proj[(size_t)sj * DD + 4 * l];
            acc.x = fmaf(p.x, wj, acc.x);
            acc.y = fmaf(p.y, wj, acc.y);
            acc.z = fmaf(p.z, wj, acc.z);
            acc.w = fmaf(p.w, wj, acc.w);
        }
        __syncwarp();
    }
    const float inv = 1.f / dn;
    *(float4*)&g_act[(size_t)n * DD + 4 * l] =
        make_float4(acc.x * inv, acc.y * inv, acc.z * inv, acc.w * inv);
}

// ---------------- hierarchical pool (flush-on-graph-change) ----------------
__global__ void pool2_kernel(const int* __restrict__ batch,
                             const float* __restrict__ b3) {
    const int t = threadIdx.x;          // 256
    const int d = t & 63;
    const int r = t >> 6;               // 0..3
    const int start = blockIdx.x * 256;
    const float bias = b3[d];
    int curg = -1;
    float accv = 0.f, accc = 0.f;
    for (int k = 0; k < 64; k++) {
        int n = start + r + k * 4;
        if (n >= NN) break;
        int g = batch[n];
        if (g != curg) {
            if (curg >= 0) {
                atomicAdd(&g_sums[curg * DD + d], accv);
                if (d == 0) atomicAdd(&g_cnt[curg], accc);
            }
            curg = g; accv = 0.f; accc = 0.f;
        }
        float v = g_act[(size_t)n * DD + d] + bias;
        v = v > 0.f ? v : expm1f(v);
        accv += v;
        accc += 1.f;
    }
    if (curg >= 0) {
        atomicAdd(&g_sums[curg * DD + d], accv);
        if (d == 0) atomicAdd(&g_cnt[curg], accc);
    }
}

// ---------------- final linear (+ re-zero pool buffers) ---------------------
__global__ void final_kernel(const float* __restrict__ lin_W,
                             const float* __restrict__ lin_b,
                             float* __restrict__ out) {
    int t = threadIdx.x;                // 640
    int g = t / NCLS;
    int c = t % NCLS;
    float cnt = fmaxf(g_cnt[g], 1.0f);
    float acc = lin_b[c];
#pragma unroll
    for (int d = 0; d < DD; d++)
        acc = fmaf(g_sums[g * DD + d] / cnt, lin_W[d * NCLS + c], acc);
    out[g * NCLS + c] = acc;
    __syncthreads();
    for (int i = t; i < GG * DD; i += 640) g_sums[i] = 0.f;
    if (t < GG) g_cnt[t] = 0.f;
}

// ---------------- launch ----------------
extern "C" void kernel_launch(void* const* d_in, const int* in_sizes, int n_in,
                              void* d_out, int out_size) {
    const float* x      = (const float*)d_in[0];
    const int*   ei     = (const int*)  d_in[1];
    const int*   batch  = (const int*)  d_in[2];
    const float* W1     = (const float*)d_in[3];
    const float* a1s    = (const float*)d_in[4];
    const float* a1d    = (const float*)d_in[5];
    const float* b1     = (const float*)d_in[6];
    const float* W2     = (const float*)d_in[7];
    const float* a2s    = (const float*)d_in[8];
    const float* a2d    = (const float*)d_in[9];
    const float* b2     = (const float*)d_in[10];
    const float* W3     = (const float*)d_in[11];
    const float* a3s    = (const float*)d_in[12];
    const float* a3d    = (const float*)d_in[13];
    const float* b3     = (const float*)d_in[14];
    const float* lin_W  = (const float*)d_in[15];
    const float* lin_b  = (const float*)d_in[16];
    float* out = (float*)d_out;

    const int ngrid = NN / 32;
    const int egrid = NN / (2 * EW);    // 6250
    const int etg   = (ET + 255) / 256;
    const int pgrid = (NN + 255) / 256;

    hist_kernel<<<etg, 256>>>(ei);                                         // 0
    scanF_kernel<<<1, 1024>>>();                                           // 1
    scatter_kernel<<<etg, 256>>>(ei);                                      // 2
    gemm_al_kernel<FIN, true><<<ngrid, 256>>>(x, W1, a1s, a1d, nullptr);   // 3 (profiled)
    edge_csr_kernel<<<egrid, 256>>>();                                     // 4

    gemm_al_kernel<DD, false><<<ngrid, 256>>>(nullptr, W2, a2s, a2d, b1);  // 5
    edge_csr_kernel<<<egrid, 256>>>();                                     // 6

    gemm_al_kernel<DD, false><<<ngrid, 256>>>(nullptr, W3, a3s, a3d, b2);  // 7
    edge_csr_kernel<<<egrid, 256>>>();                                     // 8

    pool2_kernel<<<pgrid, 256>>>(batch, b3);                               // 9
    final_kernel<<<1, GG * NCLS>>>(lin_W, lin_b, out);                     // 10
}

// round 11
// speedup vs baseline: 2.0452x; 1.0806x over previous
#include <cuda_runtime.h>
#include <math.h>

#define NN   100000
#define EE   1600000
#define ET   (EE + NN)     // edges + self loops
#define FIN  128
#define DD   64
#define HH   8
#define GG   64
#define NCLS 10
#define SLOPE 0.2f

#define SCAT_BLOCKS ((ET + 255) / 256)   // 6641

// ---------------- scratch (device globals) ----------------
__device__ float g_proj[NN * DD];        // h = I @ W (fp32)
__device__ float g_act [NN * DD];        // normalized layer output
__device__ float g_als [NN * HH];
__device__ float g_ald [NN * HH];
__device__ int   g_rowptr[NN + 1];
__device__ int   g_col [ET];
__device__ int   g_cnti[NN];             // zero-init; re-zeroed by scatter tail
__device__ int   g_rank[ET];
__device__ float g_sums[GG * DD];        // zero-init; re-zeroed by final tail
__device__ float g_cnt [GG];

// ---------------- CSR build ----------------
__global__ void hist_kernel(const int* __restrict__ ei) {
    int i = blockIdx.x * blockDim.x + threadIdx.x;
    if (i >= ET) return;
    int dst = (i < EE) ? ei[EE + i] : (i - EE);
    g_rank[i] = atomicAdd(&g_cnti[dst], 1);
}

// Single-block fused exclusive scan of g_cnti -> g_rowptr.
__global__ void scanF_kernel() {
    __shared__ int wsum[32];
    __shared__ int woff[32];
    __shared__ int tot;
    const int t = threadIdx.x;
    const int lane = t & 31, wid = t >> 5;
    int run = 0;
    for (int chunk = 0; chunk < 98; chunk++) {
        int idx = chunk * 1024 + t;
        int v = (idx < NN) ? g_cnti[idx] : 0;
        int inc = v;
#pragma unroll
        for (int off = 1; off < 32; off <<= 1) {
            int x = __shfl_up_sync(0xffffffffu, inc, off);
            if (lane >= off) inc += x;
        }
        if (lane == 31) wsum[wid] = inc;
        __syncthreads();
        if (wid == 0) {
            int s = wsum[lane];
            int is = s;
#pragma unroll
            for (int off = 1; off < 32; off <<= 1) {
                int x = __shfl_up_sync(0xffffffffu, is, off);
                if (lane >= off) is += x;
            }
            woff[lane] = is - s;
            if (lane == 31) tot = is;
        }
        __syncthreads();
        if (idx < NN) g_rowptr[idx] = run + woff[wid] + (inc - v);
        run += tot;
    }
    if (t == 0) g_rowptr[NN] = run;
}

// ---------------- GEMM body: 64 nodes x 64 cols tile, 4x4/thread ------------
template<int K, bool FIRST>
__device__ __forceinline__ void gemm_body(int bid,
                                          const float* __restrict__ I,
                                          const float* __restrict__ W,
                                          const float* __restrict__ a_src,
                                          const float* __restrict__ a_dst,
                                          const float* __restrict__ prev_bias) {
    __shared__ float xs[64][68];
    __shared__ float Wsm[64][64];
    const int t  = threadIdx.x;
    const int tx = t & 15;
    const int ty = t >> 4;
    const int node0 = bid * 64;

    float acc[4][4];
#pragma unroll
    for (int i = 0; i < 4; i++)
#pragma unroll
        for (int j = 0; j < 4; j++) acc[i][j] = 0.f;

    for (int kc = 0; kc < K; kc += 64) {
        // stage xs: 64 nodes x 64 k (1024 float4, 4 per thread)
#pragma unroll
        for (int it = 0; it < 4; it++) {
            int fid  = t + it * 256;
            int node = fid >> 4;
            int kq   = (fid & 15) * 4;
            int gn   = node0 + node;
            float4 v = make_float4(0.f, 0.f, 0.f, 0.f);
            if (gn < NN) {
                if (FIRST) {
                    v = *(const float4*)&I[(size_t)gn * K + kc + kq];
                } else {
                    v = *(const float4*)&g_act[(size_t)gn * K + kc + kq];
                    v.x += prev_bias[kc + kq    ];
                    v.y += prev_bias[kc + kq + 1];
                    v.z += prev_bias[kc + kq + 2];
                    v.w += prev_bias[kc + kq + 3];
                    v.x = v.x > 0.f ? v.x : expm1f(v.x);
                    v.y = v.y > 0.f ? v.y : expm1f(v.y);
                    v.z = v.z > 0.f ? v.z : expm1f(v.z);
                    v.w = v.w > 0.f ? v.w : expm1f(v.w);
                }
            }
            *(float4*)&xs[node][kq] = v;
        }
        // stage W chunk: 64 x 64 (1024 float4, 4 per thread)
#pragma unroll
        for (int it = 0; it < 4; it++) {
            int fid = t + it * 256;
            int kk  = fid >> 4;
            int cq  = (fid & 15) * 4;
            *(float4*)&Wsm[kk][cq] = *(const float4*)&W[(size_t)(kc + kk) * DD + cq];
        }
        __syncthreads();
#pragma unroll
        for (int k = 0; k < 64; k++) {
            float4 wv = *(const float4*)&Wsm[k][tx * 4];
            float xv0 = xs[4 * ty    ][k];
            float xv1 = xs[4 * ty + 1][k];
            float xv2 = xs[4 * ty + 2][k];
            float xv3 = xs[4 * ty + 3][k];
            acc[0][0] = fmaf(xv0, wv.x, acc[0][0]);
            acc[0][1] = fmaf(xv0, wv.y, acc[0][1]);
            acc[0][2] = fmaf(xv0, wv.z, acc[0][2]);
            acc[0][3] = fmaf(xv0, wv.w, acc[0][3]);
            acc[1][0] = fmaf(xv1, wv.x, acc[1][0]);
            acc[1][1] = fmaf(xv1, wv.y, acc[1][1]);
            acc[1][2] = fmaf(xv1, wv.z, acc[1][2]);
            acc[1][3] = fmaf(xv1, wv.w, acc[1][3]);
            acc[2][0] = fmaf(xv2, wv.x, acc[2][0]);
            acc[2][1] = fmaf(xv2, wv.y, acc[2][1]);
            acc[2][2] = fmaf(xv2, wv.z, acc[2][2]);
            acc[2][3] = fmaf(xv2, wv.w, acc[2][3]);
            acc[3][0] = fmaf(xv3, wv.x, acc[3][0]);
            acc[3][1] = fmaf(xv3, wv.y, acc[3][1]);
            acc[3][2] = fmaf(xv3, wv.z, acc[3][2]);
            acc[3][3] = fmaf(xv3, wv.w, acc[3][3]);
        }
        __syncthreads();
    }

#pragma unroll
    for (int i = 0; i < 4; i++) {
        int gn = node0 + 4 * ty + i;
        if (gn < NN)
            *(float4*)&g_proj[(size_t)gn * DD + tx * 4] =
                make_float4(acc[i][0], acc[i][1], acc[i][2], acc[i][3]);
    }

    // attention logits: head tx>>1 (cols 8h..8h+7 split across tx, tx^1)
#pragma unroll
    for (int i = 0; i < 4; i++) {
        float s = 0.f, d = 0.f;
#pragma unroll
        for (int j = 0; j < 4; j++) {
            int c = tx * 4 + j;
            s = fmaf(acc[i][j], a_src[c], s);
            d = fmaf(acc[i][j], a_dst[c], d);
        }
        s += __shfl_xor_sync(0xffffffffu, s, 1);
        d += __shfl_xor_sync(0xffffffffu, d, 1);
        int gn = node0 + 4 * ty + i;
        if ((tx & 1) == 0 && gn < NN) {
            int h = tx >> 1;
            g_als[gn * HH + h] = s;
            g_ald[gn * HH + h] = d;
        }
    }
}

// ---------------- fused scatter + layer-1 GEMM ------------------------------
// Blocks [0, SCAT_BLOCKS): CSR scatter (atomic-free via g_rank) + g_cnti re-zero.
// Blocks [SCAT_BLOCKS, ...): layer-1 GEMM tiles. Independent work -> overlap.
__global__ void scatter_gemm1_kernel(const int* __restrict__ ei,
                                     const float* __restrict__ x,
                                     const float* __restrict__ W1,
                                     const float* __restrict__ a1s,
                                     const float* __restrict__ a1d) {
    if (blockIdx.x < SCAT_BLOCKS) {
        int i = blockIdx.x * 256 + threadIdx.x;
        if (i < NN) g_cnti[i] = 0;
        if (i >= ET) return;
        int src, dst;
        if (i < EE) { src = ei[i]; dst = ei[EE + i]; }
        else        { src = dst = i - EE; }
        g_col[g_rowptr[dst] + g_rank[i]] = src;
    } else {
        gemm_body<FIN, true>(blockIdx.x - SCAT_BLOCKS, x, W1, a1s, a1d, nullptr);
    }
}

// ---------------- standalone GEMM (layers 2/3) ------------------------------
template<int K>
__global__ void gemm_al_kernel(const float* __restrict__ W,
                               const float* __restrict__ a_src,
                               const float* __restrict__ a_dst,
                               const float* __restrict__ prev_bias) {
    gemm_body<K, false>(blockIdx.x, nullptr, W, a_src, a_dst, prev_bias);
}

// ---------------- dual-dst CSR edge kernel (locked R9 config) ---------------
#define EW 8
__global__ void __launch_bounds__(256) edge_csr_kernel() {
    __shared__ int   ss[EW][2][16];
    __shared__ float ws[EW][2][16][9];
    const int wl   = threadIdx.x >> 5;
    const int lane = threadIdx.x & 31;
    const int half = lane >> 4;
    const int l    = lane & 15;
    const int hh   = l >> 1;
    const int n = blockIdx.x * (2 * EW) + 2 * wl + half;

    const int rs = g_rowptr[n], re = g_rowptr[n + 1];
    const int len  = re - rs;
    const int olen = __shfl_xor_sync(0xffffffffu, len, 16);
    const int mlen = max(len, olen);

    const float4 ad0 = *(const float4*)&g_ald[n * HH];
    const float4 ad1 = *(const float4*)&g_ald[n * HH + 4];

    float4 acc = make_float4(0.f, 0.f, 0.f, 0.f);
    float dn = 0.f;

    for (int base = 0; base < mlen; base += 16) {
        const int e = rs + base + l;
        const bool valid = (e < re);
        int src = valid ? g_col[e] : 0;
        ss[wl][half][l] = src;
        {
            float4 s0 = *(const float4*)&g_als[src * HH];
            float4 s1 = *(const float4*)&g_als[src * HH + 4];
            float ev[8] = { s0.x + ad0.x, s0.y + ad0.y, s0.z + ad0.z, s0.w + ad0.w,
                            s1.x + ad1.x, s1.y + ad1.y, s1.z + ad1.z, s1.w + ad1.w };
            const float m = valid ? 1.f : 0.f;
#pragma unroll
            for (int k = 0; k < 8; k++) {
                float v = ev[k] > 0.f ? ev[k] : SLOPE * ev[k];
                ws[wl][half][l][k] = m * __expf(v);
            }
        }
        __syncwarp();
        const int cnt = min(16, mlen - base);
#pragma unroll 4
        for (int j = 0; j < cnt; j++) {
            int   sj = ss[wl][half][j];
            float wj = ws[wl][half][j][hh];
            dn += wj;
            float4 p = *(const float4*)&g_proj[(size_t)sj * DD + 4 * l];
            acc.x = fmaf(p.x, wj, acc.x);
            acc.y = fmaf(p.y, wj, acc.y);
            acc.z = fmaf(p.z, wj, acc.z);
            acc.w = fmaf(p.w, wj, acc.w);
        }
        __syncwarp();
    }
    const float inv = 1.f / dn;
    *(float4*)&g_act[(size_t)n * DD + 4 * l] =
        make_float4(acc.x * inv, acc.y * inv, acc.z * inv, acc.w * inv);
}

// ---------------- hierarchical pool (flush-on-graph-change) ----------------
__global__ void pool2_kernel(const int* __restrict__ batch,
                             const float* __restrict__ b3) {
    const int t = threadIdx.x;          // 256
    const int d = t & 63;
    const int r = t >> 6;
    const int start = blockIdx.x * 256;
    const float bias = b3[d];
    int curg = -1;
    float accv = 0.f, accc = 0.f;
    for (int k = 0; k < 64; k++) {
        int n = start + r + k * 4;
        if (n >= NN) break;
        int g = batch[n];
        if (g != curg) {
            if (curg >= 0) {
                atomicAdd(&g_sums[curg * DD + d], accv);
                if (d == 0) atomicAdd(&g_cnt[curg], accc);
            }
            curg = g; accv = 0.f; accc = 0.f;
        }
        float v = g_act[(size_t)n * DD + d] + bias;
        v = v > 0.f ? v : expm1f(v);
        accv += v;
        accc += 1.f;
    }
    if (curg >= 0) {
        atomicAdd(&g_sums[curg * DD + d], accv);
        if (d == 0) atomicAdd(&g_cnt[curg], accc);
    }
}

// ---------------- final linear (+ re-zero pool buffers) ---------------------
__global__ void final_kernel(const float* __restrict__ lin_W,
                             const float* __restrict__ lin_b,
                             float* __restrict__ out) {
    int t = threadIdx.x;                // 640
    int g = t / NCLS;
    int c = t % NCLS;
    float cnt = fmaxf(g_cnt[g], 1.0f);
    float acc = lin_b[c];
#pragma unroll
    for (int d = 0; d < DD; d++)
        acc = fmaf(g_sums[g * DD + d] / cnt, lin_W[d * NCLS + c], acc);
    out[g * NCLS + c] = acc;
    __syncthreads();
    for (int i = t; i < GG * DD; i += 640) g_sums[i] = 0.f;
    if (t < GG) g_cnt[t] = 0.f;
}

// ---------------- launch ----------------
extern "C" void kernel_launch(void* const* d_in, const int* in_sizes, int n_in,
                              void* d_out, int out_size) {
    const float* x      = (const float*)d_in[0];
    const int*   ei     = (const int*)  d_in[1];
    const int*   batch  = (const int*)  d_in[2];
    const float* W1     = (const float*)d_in[3];
    const float* a1s    = (const float*)d_in[4];
    const float* a1d    = (const float*)d_in[5];
    const float* b1     = (const float*)d_in[6];
    const float* W2     = (const float*)d_in[7];
    const float* a2s    = (const float*)d_in[8];
    const float* a2d    = (const float*)d_in[9];
    const float* b2     = (const float*)d_in[10];
    const float* W3     = (const float*)d_in[11];
    const float* a3s    = (const float*)d_in[12];
    const float* a3d    = (const float*)d_in[13];
    const float* b3     = (const float*)d_in[14];
    const float* lin_W  = (const float*)d_in[15];
    const float* lin_b  = (const float*)d_in[16];
    float* out = (float*)d_out;

    const int ngrid = (NN + 63) / 64;         // 1563
    const int egrid = NN / (2 * EW);          // 6250
    const int etg   = (ET + 255) / 256;
    const int pgrid = (NN + 255) / 256;

    hist_kernel<<<etg, 256>>>(ei);                                          // 0
    scanF_kernel<<<1, 1024>>>();                                            // 1
    scatter_gemm1_kernel<<<SCAT_BLOCKS + ngrid, 256>>>(ei, x, W1, a1s, a1d);// 2
    edge_csr_kernel<<<egrid, 256>>>();                                      // 3 (profiled)

    gemm_al_kernel<DD><<<ngrid, 256>>>(W2, a2s, a2d, b1);                   // 4
    edge_csr_kernel<<<egrid, 256>>>();                                      // 5

    gemm_al_kernel<DD><<<ngrid, 256>>>(W3, a3s, a3d, b2);                   // 6
    edge_csr_kernel<<<egrid, 256>>>();                                      // 7

    pool2_kernel<<<pgrid, 256>>>(batch, b3);                                // 8
    final_kernel<<<1, GG * NCLS>>>(lin_W, lin_b, out);                      // 9
}